// round 5
// baseline (speedup 1.0000x reference)
#include <cuda_runtime.h>
#include <cuda_bf16.h>

// kspaceMap: out (32,129,128,128) f32.
//   channels 0..127: sep[b,w,h,w'] = (Re(t)cos(2pi w w'/128) - Im(t)sin(..))/128,
//                    t = row DFT_128 of input[:,0]. sep[128-w] == sep[w] (real input).
//   channel 128:     copy of input[b,1,:,:].  mask unused.
//
// R5: single fused kernel, CTA = (w=0..64, b). Each CTA redundantly computes DFT
// bin w for all 128 rows (same total FLOPs as a shared prepass), then writes its
// 64KB channel slab + mirror slab fully contiguously (STG.128, .cs). No scratch,
// no second launch. Two h-half passes keep smem at ~36KB (occ 6).

#define IM  128
#define BZ  32
#define CH_OUT 129

typedef unsigned long long u64;

static __device__ __forceinline__ u64 f2x(float a, float b) {
    u64 r; asm("mov.b64 %0, {%1, %2};" : "=l"(r) : "f"(a), "f"(b)); return r;
}
static __device__ __forceinline__ u64 mul2(u64 a, u64 b) {
    u64 d; asm("mul.rn.f32x2 %0, %1, %2;" : "=l"(d) : "l"(a), "l"(b)); return d;
}
static __device__ __forceinline__ u64 fma2(u64 a, u64 b, u64 c) {
    u64 d; asm("fma.rn.f32x2 %0, %1, %2, %3;" : "=l"(d) : "l"(a), "l"(b), "l"(c)); return d;
}
static __device__ __forceinline__ float2 unpk(u64 v) {
    float2 r; asm("mov.b64 {%0, %1}, %2;" : "=f"(r.x), "=f"(r.y) : "l"(v)); return r;
}

__global__ void __launch_bounds__(256) kspace_fused(const float* __restrict__ in,
                                                    float* __restrict__ out)
{
    const int w   = blockIdx.x;          // 0..64
    const int b   = blockIdx.y;          // 0..31
    const int tid = threadIdx.x;

    __shared__ float  xs[64 * 129];      // 64 input rows, stride-129 pad
    __shared__ float  pre[256], pim[256];
    __shared__ float2 tws[64];           // t[b, h_local, w] / 128

    // ---- hoisted twiddles ----
    // DFT: step theta_w = pi*w/64; start angle for u-quarter q: q*w*pi/2 (exact).
    const int q  = tid >> 6;             // u-quarter 0..3 (warp-uniform)
    const int hl = tid & 63;             // local row (32 consecutive per warp)
    float SS, SC;  sincospif((float)w * (1.0f / 64.0f), &SS, &SC);
    float s_in, c_in;  sincospif((float)(q * w) * 0.5f, &s_in, &c_in);

    // Store: thread owns w' = (tid&31)*4 + k, fixed; angle = pi*(w*w' mod 128)/64.
    float sc[4], ss[4];
    #pragma unroll
    for (int k = 0; k < 4; ++k) {
        const int m = (w * ((tid & 31) * 4 + k)) & (IM - 1);
        sincospif((float)m * (1.0f / 64.0f), &ss[k], &sc[k]);
    }
    const u64 C01 = f2x(sc[0], sc[1]), S01 = f2x(ss[0], ss[1]);
    const u64 C23 = f2x(sc[2], sc[3]), S23 = f2x(ss[2], ss[3]);

    const unsigned in0   = ((unsigned)b) << 15;                       // input[b,0]
    const unsigned in1   = in0 + (1u << 14);                          // input[b,1]
    const unsigned chA   = ((unsigned)(b * CH_OUT + w))        << 14;
    const unsigned chM   = ((unsigned)(b * CH_OUT + (IM - w))) << 14;
    const unsigned chCp  = ((unsigned)(b * CH_OUT + IM))       << 14;
    const bool dm     = (w >= 1) && (w <= 63);
    const bool docopy = (w == 64);

    #pragma unroll 1
    for (int pass = 0; pass < 2; ++pass) {
        __syncthreads();                 // guard xs/pre/pim reuse across passes

        // Stage 64 rows (8192 floats), coalesced LDG -> padded STS.
        {
            const unsigned src = in0 + (unsigned)pass * 8192u;
            #pragma unroll 8
            for (int j = 0; j < 32; ++j) {
                const int idx = j * 256 + tid;
                xs[(idx >> 7) * 129 + (idx & 127)] = in[src + (unsigned)idx];
            }
        }
        __syncthreads();

        // DFT bin w, row hl, u in [32q, 32q+32): rotation recurrence.
        {
            float re = 0.0f, im = 0.0f, c = c_in, s = s_in;
            const float* xp = xs + hl * 129 + (q << 5);  // conflict-free (stride-129)
            #pragma unroll 8
            for (int i = 0; i < 32; ++i) {
                const float xv = xp[i];
                re = fmaf(xv,  c, re);
                im = fmaf(xv, -s, im);
                const float cn = fmaf(c, SC, -(s * SS));
                s = fmaf(s, SC, c * SS);
                c = cn;
            }
            pre[tid] = re;  pim[tid] = im;
        }
        __syncthreads();
        if (tid < 64) {
            const float rr = pre[tid] + pre[tid + 64] + pre[tid + 128] + pre[tid + 192];
            const float ii = pim[tid] + pim[tid + 64] + pim[tid + 128] + pim[tid + 192];
            tws[tid] = make_float2(rr * (1.0f / IM), ii * (1.0f / IM));
        }
        __syncthreads();

        // Contiguous half-slab stores: 8192 floats, thread covers tid*4 + it*1024.
        {
            const unsigned poff = (unsigned)pass * 8192u + (unsigned)tid * 4u;
            #pragma unroll
            for (int it = 0; it < 8; ++it) {
                const float2 tt = tws[it * 8 + (tid >> 5)];   // LDS broadcast
                const u64 trx = f2x(tt.x, tt.x);
                const float nti = -tt.y;
                const u64 ntx = f2x(nti, nti);
                const u64 v01 = fma2(ntx, S01, mul2(trx, C01));
                const u64 v23 = fma2(ntx, S23, mul2(trx, C23));
                const float2 a = unpk(v01), d = unpk(v23);
                const float4 vv = make_float4(a.x, a.y, d.x, d.y);
                const unsigned off = poff + (unsigned)it * 1024u;
                __stcs((float4*)(out + chA + off), vv);
                if (dm) __stcs((float4*)(out + chM + off), vv);
                if (docopy) {
                    const float4 cp = __ldcs((const float4*)(in + in1 + off));
                    __stcs((float4*)(out + chCp + off), cp);
                }
            }
        }
    }
}

extern "C" void kernel_launch(void* const* d_in, const int* in_sizes, int n_in,
                              void* d_out, int out_size)
{
    const float* in  = (const float*)d_in[0];   // (32,2,128,128) f32
    float*       out = (float*)d_out;           // (32,129,128,128) f32
    (void)in_sizes; (void)n_in; (void)out_size;

    kspace_fused<<<dim3(65, BZ), 256>>>(in, out);
}